// round 4
// baseline (speedup 1.0000x reference)
#include <cuda_runtime.h>
#include <math.h>

// ---------------------------------------------------------------------------
// EvidentialGNN3D, CSR-sorted formulation.
//  Build once:  geo=(len,dot1,dot2) per edge, edges counting-sorted by dst.
//  Per round :  msg_j = tanh(h[f][j] + len*W10 + dot1*W12 + dot2*W13),
//               sorted-dst vector-RED scatter into padded state rows.
//  h[f] = state[f]@Ws + b + sum|c_f|*W11  (per node, fused copy to next buf).
// ---------------------------------------------------------------------------

#define NMAX 200064
#define EMAX 6400000
#define GMAX 2048
#define SDP  12

__device__ float4 g_state[2][NMAX * 3];   // ping-pong state (N,12)
__device__ float4 g_h[NMAX * 3];          // per-node h (N,12)
__device__ float4 g_pc[NMAX];             // (x,y,z,sum|c|)
__device__ float4 g_gs[GMAX * 3];         // per-graph accum
__device__ int    g_cnt[NMAX];            // per-dst degree counts
__device__ int    g_woff[NMAX];           // write cursors (CSR offsets)
__device__ int    g_bsums[1056];          // block sums for scan
__device__ float4 g_rec[EMAX];            // sorted records (len,dot1,dot2,f)
__device__ int    g_dst[EMAX];            // sorted destinations

__device__ __forceinline__ float tanh_fast(float x) {
    float e = __expf(2.0f * x);
    return 1.0f - __fdividef(2.0f, e + 1.0f);
}
__device__ __forceinline__ void red_add4(float* p, float a, float b, float c, float d) {
    unsigned long long gp = __cvta_generic_to_global((void*)p);
    asm volatile("red.global.add.v4.f32 [%0], {%1,%2,%3,%4};"
                 :: "l"(gp), "f"(a), "f"(b), "f"(c), "f"(d) : "memory");
}
__device__ __forceinline__ void red_add2(float* p, float a, float b) {
    unsigned long long gp = __cvta_generic_to_global((void*)p);
    asm volatile("red.global.add.v2.f32 [%0], {%1,%2};"
                 :: "l"(gp), "f"(a), "f"(b) : "memory");
}

// ---- init: pc, h0 = b + sum|c|*W11, zero both state bufs, counts, g_gs ----
__global__ void k_init(const float* __restrict__ coords,
                       const float* __restrict__ Wm, const float* __restrict__ bm,
                       int N) {
    int n = blockIdx.x * blockDim.x + threadIdx.x;
    float4 z4 = make_float4(0.f, 0.f, 0.f, 0.f);
    if (n < N) {
        float x = coords[3 * n + 0];
        float y = coords[3 * n + 1];
        float z = coords[3 * n + 2];
        float sa = fabsf(x) + fabsf(y) + fabsf(z);
        g_pc[n] = make_float4(x, y, z, sa);
        float h[10];
#pragma unroll
        for (int j = 0; j < 10; j++)
            h[j] = fmaf(sa, __ldg(&Wm[110 + j]), __ldg(&bm[j]));
        float4* hrow = &g_h[n * 3];
        hrow[0] = make_float4(h[0], h[1], h[2], h[3]);
        hrow[1] = make_float4(h[4], h[5], h[6], h[7]);
        hrow[2] = make_float4(h[8], h[9], 0.f, 0.f);
#pragma unroll
        for (int k = 0; k < 3; k++) {
            g_state[0][n * 3 + k] = z4;
            g_state[1][n * 3 + k] = z4;
        }
        g_cnt[n] = 0;
    }
    if (n < GMAX) {
        g_gs[n * 3 + 0] = z4;
        g_gs[n * 3 + 1] = z4;
        g_gs[n * 3 + 2] = z4;
    }
}

// ---- histogram of destinations ----
__global__ void k_hist(const int* __restrict__ eto, int E) {
    int e = blockIdx.x * blockDim.x + threadIdx.x;
    if (e < E) atomicAdd(&g_cnt[eto[e]], 1);
}

// ---- 3-phase exclusive scan of g_cnt (N <= 1024*256) ----
__global__ void k_bsum(int N, int NB) {
    int b = blockIdx.x, t = threadIdx.x;
    int i = b * 256 + t;
    int v = (i < N) ? g_cnt[i] : 0;
    __shared__ int sm[256];
    sm[t] = v; __syncthreads();
    for (int s = 128; s > 0; s >>= 1) {
        if (t < s) sm[t] += sm[t + s];
        __syncthreads();
    }
    if (t == 0) g_bsums[b] = sm[0];
}
__global__ void k_scanb(int NB) {   // 1 block, 1024 threads; NB <= 1024
    __shared__ int sm[1024];
    int t = threadIdx.x;
    int own = (t < NB) ? g_bsums[t] : 0;
    sm[t] = own; __syncthreads();
    for (int d = 1; d < 1024; d <<= 1) {
        int add = (t >= d) ? sm[t - d] : 0;
        __syncthreads();
        sm[t] += add;
        __syncthreads();
    }
    g_bsums[t] = sm[t] - own;   // exclusive
}
__global__ void k_offsets(int N) {
    int b = blockIdx.x, t = threadIdx.x;
    int i = b * 256 + t;
    int own = (i < N) ? g_cnt[i] : 0;
    __shared__ int sm[256];
    sm[t] = own; __syncthreads();
    for (int d = 1; d < 256; d <<= 1) {
        int add = (t >= d) ? sm[t - d] : 0;
        __syncthreads();
        sm[t] += add;
        __syncthreads();
    }
    if (i < N) g_woff[i] = g_bsums[b] + sm[t] - own;   // exclusive offset
}

// ---- build sorted records: geo + source, counting-sort by dst ----
__global__ void k_build(const int* __restrict__ efrom, const int* __restrict__ eto,
                        const float* __restrict__ elen, const float* __restrict__ evec,
                        int E) {
    int e = blockIdx.x * blockDim.x + threadIdx.x;
    if (e >= E) return;
    int f = efrom[e];
    int t = eto[e];
    float4 cf = g_pc[f];
    float4 ct = g_pc[t];
    float len = elen[e];
    float v0 = evec[3 * e + 0];
    float v1 = evec[3 * e + 1];
    float v2 = evec[3 * e + 2];
    float dot1 = fmaf(cf.x, ct.x, fmaf(cf.y, ct.y, cf.z * ct.z));
    float dot2 = fmaf(cf.x, v0, fmaf(cf.y, v1, cf.z * v2));
    int pos = atomicAdd(&g_woff[t], 1);
    g_rec[pos] = make_float4(len, dot1, dot2, __int_as_float(f));
    g_dst[pos] = t;
}

// ---- per-node h = state@Ws + b + sa*W11 ; copy state -> next ----
__global__ void k_h(const float* __restrict__ Wm, const float* __restrict__ bm,
                    int N, int cur) {
    int n = blockIdx.x * blockDim.x + threadIdx.x;
    if (n >= N) return;
    const float4* srow = &g_state[cur][n * 3];
    float4 s0 = srow[0], s1 = srow[1], s2 = srow[2];
    float s[10] = { s0.x, s0.y, s0.z, s0.w, s1.x, s1.y, s1.z, s1.w, s2.x, s2.y };
    float sa = g_pc[n].w;
    float h[10];
#pragma unroll
    for (int j = 0; j < 10; j++) {
        float acc = fmaf(sa, __ldg(&Wm[110 + j]), __ldg(&bm[j]));
#pragma unroll
        for (int i = 0; i < 10; i++)
            acc = fmaf(s[i], __ldg(&Wm[i * 10 + j]), acc);
        h[j] = acc;
    }
    float4* hrow = &g_h[n * 3];
    hrow[0] = make_float4(h[0], h[1], h[2], h[3]);
    hrow[1] = make_float4(h[4], h[5], h[6], h[7]);
    hrow[2] = make_float4(h[8], h[9], 0.f, 0.f);
    float4* drow = &g_state[cur ^ 1][n * 3];
    drow[0] = s0; drow[1] = s1; drow[2] = s2;
}

// ---- per-edge (sorted): 3 gathers + 30 FMA + tanh + locality-friendly REDs ----
__global__ void __launch_bounds__(256)
k_edge(int E, int nxt, int T) {
    int tid = blockIdx.x * blockDim.x + threadIdx.x;
    extern __shared__ float dummy[];
    float wl[10], w2[10], w3[10];
    {
        // weights cached in g_h? no — read via constant-ish global (hot L1)
    }
    // load weights from global Wm snapshot stored in g_bsums? keep via param-free:
    // (weights are re-read from global each launch; passed through g_rec? No —
    //  simplest: stash them in __constant__-like global below.)
    // -- replaced below by g_w
    for (int e = tid; e < E; e += T) (void)0;  // placeholder removed
}

// weight stash filled once per round-set (k_wld)
__device__ float g_w[30];
__global__ void k_wld(const float* __restrict__ Wm) {
    int j = threadIdx.x;
    if (j < 10) {
        g_w[j]      = Wm[100 + j];
        g_w[10 + j] = Wm[120 + j];
        g_w[20 + j] = Wm[130 + j];
    }
}

__global__ void __launch_bounds__(256)
k_edge2(int E, int nxt, int T) {
    int tid = blockIdx.x * blockDim.x + threadIdx.x;
    float wl[10], w2[10], w3[10];
#pragma unroll
    for (int j = 0; j < 10; j++) {
        wl[j] = g_w[j];
        w2[j] = g_w[10 + j];
        w3[j] = g_w[20 + j];
    }
    float* stt = (float*)&g_state[nxt][0];
    for (int e = tid; e < E; e += T) {
        float4 r = g_rec[e];
        int t = g_dst[e];
        int f = __float_as_int(r.w);
        const float4* hrow = &g_h[f * 3];
        float4 h0 = hrow[0], h1 = hrow[1], h2 = hrow[2];
        float hv[10] = { h0.x, h0.y, h0.z, h0.w, h1.x, h1.y, h1.z, h1.w, h2.x, h2.y };
        float m[10];
#pragma unroll
        for (int j = 0; j < 10; j++) {
            float a = fmaf(r.x, wl[j], fmaf(r.y, w2[j], fmaf(r.z, w3[j], hv[j])));
            m[j] = tanh_fast(a);
        }
        float* dst = stt + (size_t)t * SDP;
        red_add4(dst,     m[0], m[1], m[2], m[3]);
        red_add4(dst + 4, m[4], m[5], m[6], m[7]);
        red_add2(dst + 8, m[8], m[9]);
    }
}

// ---- graph segment sum ----
__global__ void k_graph(const int* __restrict__ gidx, int N, int fin) {
    int n = blockIdx.x * blockDim.x + threadIdx.x;
    if (n >= N) return;
    int g = gidx[n];
    const float4* srow = &g_state[fin][n * 3];
    float4 s0 = srow[0], s1 = srow[1], s2 = srow[2];
    float* dst = (float*)&g_gs[g * 3];
    red_add4(dst,     s0.x, s0.y, s0.z, s0.w);
    red_add4(dst + 4, s1.x, s1.y, s1.z, s1.w);
    red_add2(dst + 8, s2.x, s2.y);
}

__device__ __forceinline__ float softplus_acc(float x) {
    if (x > 20.f) return x;
    return log1pf(expf(x));
}

__global__ void k_out(const float* __restrict__ Wo, const float* __restrict__ bo,
                      float* __restrict__ out, int G) {
    int g = blockIdx.x * blockDim.x + threadIdx.x;
    if (g >= G) return;
    const float* gs = (const float*)&g_gs[g * 3];
    float e[4];
#pragma unroll
    for (int j = 0; j < 4; j++) {
        float acc = __ldg(&bo[j]);
#pragma unroll
        for (int i = 0; i < 10; i++)
            acc = fmaf(gs[i], __ldg(&Wo[i * 4 + j]), acc);
        e[j] = acc;
    }
    out[4 * g + 0] = e[0];
    out[4 * g + 1] = softplus_acc(e[1]);
    out[4 * g + 2] = softplus_acc(e[2]) + 1.0f;
    out[4 * g + 3] = softplus_acc(e[3]);
}

extern "C" void kernel_launch(void* const* d_in, const int* in_sizes, int n_in,
                              void* d_out, int out_size) {
    const float* coords = (const float*)d_in[0];
    const float* elen   = (const float*)d_in[1];
    const float* evec   = (const float*)d_in[2];
    const float* Wm     = (const float*)d_in[3];
    const float* bm     = (const float*)d_in[4];
    const float* Wo     = (const float*)d_in[5];
    const float* bo     = (const float*)d_in[6];
    const int*   efrom  = (const int*)d_in[7];
    const int*   eto    = (const int*)d_in[8];
    const int*   gidx   = (const int*)d_in[9];
    float* out = (float*)d_out;

    int E = in_sizes[7];
    int N = in_sizes[9];
    int G = out_size / 4;

    const int TB = 256;
    int init_count = (N > GMAX) ? N : GMAX;
    int init_blocks = (init_count + TB - 1) / TB;
    int node_blocks = (N + TB - 1) / TB;
    int edge_blocks1 = (E + TB - 1) / TB;           // 1 edge/thread
    long ethreads = ((long)E + 3) / 4;              // 4 edges/thread
    int eblocks = (int)((ethreads + TB - 1) / TB);
    int T = eblocks * TB;
    int NB = (N + 255) / 256;                       // scan blocks (<=1024)
    int gblocks = (G + TB - 1) / TB;

    // build (once per launch; graph replays re-run it — deterministic)
    k_init<<<init_blocks, TB>>>(coords, Wm, bm, N);
    k_hist<<<edge_blocks1, TB>>>(eto, E);
    k_bsum<<<NB, 256>>>(N, NB);
    k_scanb<<<1, 1024>>>(NB);
    k_offsets<<<NB, 256>>>(N);
    k_build<<<edge_blocks1, TB>>>(efrom, eto, elen, evec, E);
    k_wld<<<1, 32>>>(Wm);

    // round 0: h = h0 (from init), state[0]=0 -> RED into state[1]
    k_edge2<<<eblocks, TB>>>(E, 1, T);
    // round 1
    k_h<<<node_blocks, TB>>>(Wm, bm, N, 1);
    k_edge2<<<eblocks, TB>>>(E, 0, T);
    // round 2
    k_h<<<node_blocks, TB>>>(Wm, bm, N, 0);
    k_edge2<<<eblocks, TB>>>(E, 1, T);

    k_graph<<<node_blocks, TB>>>(gidx, N, 1);
    k_out<<<gblocks, TB>>>(Wo, bo, out, G);
}

// round 5
// speedup vs baseline: 1.1778x; 1.1778x over previous
#include <cuda_runtime.h>
#include <math.h>

// ---------------------------------------------------------------------------
// EvidentialGNN3D, CSR warp-per-node formulation (atomic-free rounds).
//  Build once/launch: geo=(len,dot1,dot2,src) counting-sorted by dst (CSR).
//  Per round: h[n] = state[n]@Ws + b + sum|c_n|*W11   (k_h)
//             warp n: state[n] += sum_{e in CSR[n]} tanh(h[src]+geo@Wg)  (k_edge)
//  No ping-pong: state updated in place by its owning warp.
// ---------------------------------------------------------------------------

#define NMAX 200064
#define EMAX 6400000
#define GMAX 2048
#define SDP  12

__device__ float4 g_state[NMAX * 3];      // state (N,12) in-place
__device__ float4 g_h[NMAX * 3];          // per-node h (N,12)
__device__ float4 g_pc[NMAX];             // (x,y,z,sum|c|)
__device__ float4 g_gs[GMAX * 3];         // per-graph accum
__device__ int    g_cnt[NMAX];            // per-dst degree
__device__ int    g_rs[NMAX];             // CSR row starts
__device__ int    g_woff[NMAX];           // scatter cursors
__device__ int    g_bsums[1056];          // scan block sums
__device__ float4 g_rec[EMAX];            // sorted (len,dot1,dot2,src_as_int)
__device__ float  g_w[30];                // W rows 10,12,13

__device__ __forceinline__ float tanh_fast(float x) {
    float e = __expf(2.0f * x);
    return 1.0f - __fdividef(2.0f, e + 1.0f);
}
__device__ __forceinline__ void red_add4(float* p, float a, float b, float c, float d) {
    unsigned long long gp = __cvta_generic_to_global((void*)p);
    asm volatile("red.global.add.v4.f32 [%0], {%1,%2,%3,%4};"
                 :: "l"(gp), "f"(a), "f"(b), "f"(c), "f"(d) : "memory");
}
__device__ __forceinline__ void red_add2(float* p, float a, float b) {
    unsigned long long gp = __cvta_generic_to_global((void*)p);
    asm volatile("red.global.add.v2.f32 [%0], {%1,%2};"
                 :: "l"(gp), "f"(a), "f"(b) : "memory");
}

// ---- init: pc, h0=b+sum|c|*W11, zero state/counts/graph accum ----
__global__ void k_init(const float* __restrict__ coords,
                       const float* __restrict__ Wm, const float* __restrict__ bm,
                       int N) {
    int n = blockIdx.x * blockDim.x + threadIdx.x;
    float4 z4 = make_float4(0.f, 0.f, 0.f, 0.f);
    if (n < N) {
        float x = coords[3 * n + 0];
        float y = coords[3 * n + 1];
        float z = coords[3 * n + 2];
        float sa = fabsf(x) + fabsf(y) + fabsf(z);
        g_pc[n] = make_float4(x, y, z, sa);
        float h[10];
#pragma unroll
        for (int j = 0; j < 10; j++)
            h[j] = fmaf(sa, __ldg(&Wm[110 + j]), __ldg(&bm[j]));
        float4* hrow = &g_h[n * 3];
        hrow[0] = make_float4(h[0], h[1], h[2], h[3]);
        hrow[1] = make_float4(h[4], h[5], h[6], h[7]);
        hrow[2] = make_float4(h[8], h[9], 0.f, 0.f);
        g_state[n * 3 + 0] = z4;
        g_state[n * 3 + 1] = z4;
        g_state[n * 3 + 2] = z4;
        g_cnt[n] = 0;
    }
    if (n < GMAX) {
        g_gs[n * 3 + 0] = z4;
        g_gs[n * 3 + 1] = z4;
        g_gs[n * 3 + 2] = z4;
    }
}

__global__ void k_hist(const int* __restrict__ eto, int E) {
    int e = blockIdx.x * blockDim.x + threadIdx.x;
    if (e < E) atomicAdd(&g_cnt[eto[e]], 1);
}

// ---- exclusive scan of g_cnt ----
__global__ void k_bsum(int N) {
    int b = blockIdx.x, t = threadIdx.x;
    int i = b * 256 + t;
    int v = (i < N) ? g_cnt[i] : 0;
    __shared__ int sm[256];
    sm[t] = v; __syncthreads();
    for (int s = 128; s > 0; s >>= 1) {
        if (t < s) sm[t] += sm[t + s];
        __syncthreads();
    }
    if (t == 0) g_bsums[b] = sm[0];
}
__global__ void k_scanb(int NB) {   // 1 block of 1024; NB <= 1024
    __shared__ int sm[1024];
    int t = threadIdx.x;
    int own = (t < NB) ? g_bsums[t] : 0;
    sm[t] = own; __syncthreads();
    for (int d = 1; d < 1024; d <<= 1) {
        int add = (t >= d) ? sm[t - d] : 0;
        __syncthreads();
        sm[t] += add;
        __syncthreads();
    }
    g_bsums[t] = sm[t] - own;
}
__global__ void k_offsets(int N) {
    int b = blockIdx.x, t = threadIdx.x;
    int i = b * 256 + t;
    int own = (i < N) ? g_cnt[i] : 0;
    __shared__ int sm[256];
    sm[t] = own; __syncthreads();
    for (int d = 1; d < 256; d <<= 1) {
        int add = (t >= d) ? sm[t - d] : 0;
        __syncthreads();
        sm[t] += add;
        __syncthreads();
    }
    if (i < N) {
        int start = g_bsums[b] + sm[t] - own;
        g_rs[i] = start;
        g_woff[i] = start;
    }
}

// ---- build sorted records ----
__global__ void k_build(const int* __restrict__ efrom, const int* __restrict__ eto,
                        const float* __restrict__ elen, const float* __restrict__ evec,
                        int E) {
    int e = blockIdx.x * blockDim.x + threadIdx.x;
    if (e >= E) return;
    int f = efrom[e];
    int t = eto[e];
    float4 cf = g_pc[f];
    float4 ct = g_pc[t];
    float len = elen[e];
    float v0 = evec[3 * e + 0];
    float v1 = evec[3 * e + 1];
    float v2 = evec[3 * e + 2];
    float dot1 = fmaf(cf.x, ct.x, fmaf(cf.y, ct.y, cf.z * ct.z));
    float dot2 = fmaf(cf.x, v0, fmaf(cf.y, v1, cf.z * v2));
    int pos = atomicAdd(&g_woff[t], 1);
    g_rec[pos] = make_float4(len, dot1, dot2, __int_as_float(f));
}

__global__ void k_wld(const float* __restrict__ Wm) {
    int j = threadIdx.x;
    if (j < 10) {
        g_w[j]      = Wm[100 + j];
        g_w[10 + j] = Wm[120 + j];
        g_w[20 + j] = Wm[130 + j];
    }
}

// ---- per-node h = state@Ws + b + sa*W11 (no copy; state is in-place) ----
__global__ void k_h(const float* __restrict__ Wm, const float* __restrict__ bm,
                    int N) {
    int n = blockIdx.x * blockDim.x + threadIdx.x;
    if (n >= N) return;
    const float4* srow = &g_state[n * 3];
    float4 s0 = srow[0], s1 = srow[1], s2 = srow[2];
    float s[10] = { s0.x, s0.y, s0.z, s0.w, s1.x, s1.y, s1.z, s1.w, s2.x, s2.y };
    float sa = g_pc[n].w;
    float h[10];
#pragma unroll
    for (int j = 0; j < 10; j++) {
        float acc = fmaf(sa, __ldg(&Wm[110 + j]), __ldg(&bm[j]));
#pragma unroll
        for (int i = 0; i < 10; i++)
            acc = fmaf(s[i], __ldg(&Wm[i * 10 + j]), acc);
        h[j] = acc;
    }
    float4* hrow = &g_h[n * 3];
    hrow[0] = make_float4(h[0], h[1], h[2], h[3]);
    hrow[1] = make_float4(h[4], h[5], h[6], h[7]);
    hrow[2] = make_float4(h[8], h[9], 0.f, 0.f);
}

// ---- warp-per-node edge pass: atomic-free segment reduction ----
__global__ void __launch_bounds__(256)
k_edge(int N) {
    int gw = (blockIdx.x * blockDim.x + threadIdx.x) >> 5;   // warp id = node
    int lane = threadIdx.x & 31;
    if (gw >= N) return;
    int n = gw;
    int row0 = g_rs[n];
    int row1 = row0 + g_cnt[n];

    float wl[10], w2[10], w3[10];
#pragma unroll
    for (int j = 0; j < 10; j++) {
        wl[j] = g_w[j];
        w2[j] = g_w[10 + j];
        w3[j] = g_w[20 + j];
    }

    float acc[10];
#pragma unroll
    for (int j = 0; j < 10; j++) acc[j] = 0.f;

    for (int e = row0 + lane; e < row1 + 31; e += 32) {
        if (e < row1) {
            float4 r = g_rec[e];
            int f = __float_as_int(r.w);
            const float4* hrow = &g_h[f * 3];
            float4 h0 = hrow[0], h1 = hrow[1], h2 = hrow[2];
            float hv[10] = { h0.x, h0.y, h0.z, h0.w,
                             h1.x, h1.y, h1.z, h1.w, h2.x, h2.y };
#pragma unroll
            for (int j = 0; j < 10; j++) {
                float a = fmaf(r.x, wl[j], fmaf(r.y, w2[j], fmaf(r.z, w3[j], hv[j])));
                acc[j] += tanh_fast(a);
            }
        }
        if (e + 32 >= row1 + 31) break;   // (loop bound handles it; keep simple)
    }

    // warp tree-reduce each feature
#pragma unroll
    for (int j = 0; j < 10; j++) {
#pragma unroll
        for (int d = 16; d > 0; d >>= 1)
            acc[j] += __shfl_down_sync(0xFFFFFFFFu, acc[j], d);
    }

    if (lane == 0) {
        float4* srow = &g_state[n * 3];
        float4 s0 = srow[0], s1 = srow[1], s2 = srow[2];
        s0.x += acc[0]; s0.y += acc[1]; s0.z += acc[2]; s0.w += acc[3];
        s1.x += acc[4]; s1.y += acc[5]; s1.z += acc[6]; s1.w += acc[7];
        s2.x += acc[8]; s2.y += acc[9];
        srow[0] = s0; srow[1] = s1; srow[2] = s2;
    }
}

// ---- graph segment sum ----
__global__ void k_graph(const int* __restrict__ gidx, int N) {
    int n = blockIdx.x * blockDim.x + threadIdx.x;
    if (n >= N) return;
    int g = gidx[n];
    const float4* srow = &g_state[n * 3];
    float4 s0 = srow[0], s1 = srow[1], s2 = srow[2];
    float* dst = (float*)&g_gs[g * 3];
    red_add4(dst,     s0.x, s0.y, s0.z, s0.w);
    red_add4(dst + 4, s1.x, s1.y, s1.z, s1.w);
    red_add2(dst + 8, s2.x, s2.y);
}

__device__ __forceinline__ float softplus_acc(float x) {
    if (x > 20.f) return x;
    return log1pf(expf(x));
}

__global__ void k_out(const float* __restrict__ Wo, const float* __restrict__ bo,
                      float* __restrict__ out, int G) {
    int g = blockIdx.x * blockDim.x + threadIdx.x;
    if (g >= G) return;
    const float* gs = (const float*)&g_gs[g * 3];
    float e[4];
#pragma unroll
    for (int j = 0; j < 4; j++) {
        float acc = __ldg(&bo[j]);
#pragma unroll
        for (int i = 0; i < 10; i++)
            acc = fmaf(gs[i], __ldg(&Wo[i * 4 + j]), acc);
        e[j] = acc;
    }
    out[4 * g + 0] = e[0];
    out[4 * g + 1] = softplus_acc(e[1]);
    out[4 * g + 2] = softplus_acc(e[2]) + 1.0f;
    out[4 * g + 3] = softplus_acc(e[3]);
}

extern "C" void kernel_launch(void* const* d_in, const int* in_sizes, int n_in,
                              void* d_out, int out_size) {
    const float* coords = (const float*)d_in[0];
    const float* elen   = (const float*)d_in[1];
    const float* evec   = (const float*)d_in[2];
    const float* Wm     = (const float*)d_in[3];
    const float* bm     = (const float*)d_in[4];
    const float* Wo     = (const float*)d_in[5];
    const float* bo     = (const float*)d_in[6];
    const int*   efrom  = (const int*)d_in[7];
    const int*   eto    = (const int*)d_in[8];
    const int*   gidx   = (const int*)d_in[9];
    float* out = (float*)d_out;

    int E = in_sizes[7];
    int N = in_sizes[9];
    int G = out_size / 4;

    const int TB = 256;
    int init_count = (N > GMAX) ? N : GMAX;
    int init_blocks = (init_count + TB - 1) / TB;
    int node_blocks = (N + TB - 1) / TB;
    int edge_blocks1 = (E + TB - 1) / TB;
    int NB = (N + 255) / 256;                 // <= 1024
    int warp_blocks = (N * 32 + TB - 1) / TB; // warp per node
    int gblocks = (G + TB - 1) / TB;

    // build (per launch; deterministic across replays)
    k_init<<<init_blocks, TB>>>(coords, Wm, bm, N);
    k_hist<<<edge_blocks1, TB>>>(eto, E);
    k_bsum<<<NB, 256>>>(N);
    k_scanb<<<1, 1024>>>(NB);
    k_offsets<<<NB, 256>>>(N);
    k_build<<<edge_blocks1, TB>>>(efrom, eto, elen, evec, E);
    k_wld<<<1, 32>>>(Wm);

    // round 0 (h = h0 from init)
    k_edge<<<warp_blocks, TB>>>(N);
    // rounds 1,2
    k_h<<<node_blocks, TB>>>(Wm, bm, N);
    k_edge<<<warp_blocks, TB>>>(N);
    k_h<<<node_blocks, TB>>>(Wm, bm, N);
    k_edge<<<warp_blocks, TB>>>(N);

    k_graph<<<node_blocks, TB>>>(gidx, N);
    k_out<<<gblocks, TB>>>(Wo, bo, out, G);
}

// round 6
// speedup vs baseline: 1.7334x; 1.4717x over previous
#include <cuda_runtime.h>
#include <cuda_fp16.h>
#include <math.h>

// ---------------------------------------------------------------------------
// EvidentialGNN3D — unsorted, geo-precomputed, in-place RED formulation.
//  Build once/launch (cheap, coalesced): rec[e] = (len, dot1, dot2, src).
//  Per round:
//    k_h   : h[n] = state[n]@Ws + b + sum|c_n|*W11   (stored fp16-packed)
//    k_edge: for each edge e: m = tanh(h[src] + geo@Wg);
//            red.global.add.v4/v2 into state[dst]  (in place; h is snapshot)
//  Readout: graph segment sum + evidential head.
// ---------------------------------------------------------------------------

#define NMAX 200064
#define EMAX 6400000
#define GMAX 2048
#define SDP  12

__device__ float4 g_state[NMAX * 3];   // (N,12) state, updated in place
__device__ uint4  g_h8[NMAX];          // h[0..7] as 8x fp16 (16B row)
__device__ unsigned int g_h9[NMAX];    // h[8..9] as 2x fp16 (4B)
__device__ float4 g_pc[NMAX];          // (x,y,z,sum|c|)
__device__ float4 g_gs[GMAX * 3];      // per-graph accum
__device__ float4 g_rec[EMAX];         // (len, dot1, dot2, src_as_int)
__device__ float  g_w[30];             // W rows 10 (len), 12 (dot1), 13 (dot2)

__device__ __forceinline__ float tanh_fast(float x) {
    float e = __expf(2.0f * x);
    return 1.0f - __fdividef(2.0f, e + 1.0f);
}
__device__ __forceinline__ void red_add4(float* p, float a, float b, float c, float d) {
    unsigned long long gp = __cvta_generic_to_global((void*)p);
    asm volatile("red.global.add.v4.f32 [%0], {%1,%2,%3,%4};"
                 :: "l"(gp), "f"(a), "f"(b), "f"(c), "f"(d) : "memory");
}
__device__ __forceinline__ void red_add2(float* p, float a, float b) {
    unsigned long long gp = __cvta_generic_to_global((void*)p);
    asm volatile("red.global.add.v2.f32 [%0], {%1,%2};"
                 :: "l"(gp), "f"(a), "f"(b) : "memory");
}

__device__ __forceinline__ void store_h(int n, const float* h) {
    __half2 p0 = __floats2half2_rn(h[0], h[1]);
    __half2 p1 = __floats2half2_rn(h[2], h[3]);
    __half2 p2 = __floats2half2_rn(h[4], h[5]);
    __half2 p3 = __floats2half2_rn(h[6], h[7]);
    __half2 p4 = __floats2half2_rn(h[8], h[9]);
    uint4 u;
    u.x = *(unsigned int*)&p0;
    u.y = *(unsigned int*)&p1;
    u.z = *(unsigned int*)&p2;
    u.w = *(unsigned int*)&p3;
    g_h8[n] = u;
    g_h9[n] = *(unsigned int*)&p4;
}

// ---- init: pc, h0 = b + sum|c|*W11 (state=0), zero state & graph accum ----
__global__ void k_init(const float* __restrict__ coords,
                       const float* __restrict__ Wm, const float* __restrict__ bm,
                       int N) {
    int n = blockIdx.x * blockDim.x + threadIdx.x;
    float4 z4 = make_float4(0.f, 0.f, 0.f, 0.f);
    if (n < N) {
        float x = coords[3 * n + 0];
        float y = coords[3 * n + 1];
        float z = coords[3 * n + 2];
        float sa = fabsf(x) + fabsf(y) + fabsf(z);
        g_pc[n] = make_float4(x, y, z, sa);
        float h[10];
#pragma unroll
        for (int j = 0; j < 10; j++)
            h[j] = fmaf(sa, __ldg(&Wm[110 + j]), __ldg(&bm[j]));
        store_h(n, h);
        g_state[n * 3 + 0] = z4;
        g_state[n * 3 + 1] = z4;
        g_state[n * 3 + 2] = z4;
    }
    if (n < GMAX) {
        g_gs[n * 3 + 0] = z4;
        g_gs[n * 3 + 1] = z4;
        g_gs[n * 3 + 2] = z4;
    }
}

// ---- one-time geo precompute (coalesced write, original edge order) ----
__global__ void k_geo(const int* __restrict__ efrom, const int* __restrict__ eto,
                      const float* __restrict__ elen, const float* __restrict__ evec,
                      int E) {
    int e = blockIdx.x * blockDim.x + threadIdx.x;
    if (e >= E) return;
    int f = efrom[e];
    int t = eto[e];
    float4 cf = g_pc[f];
    float4 ct = g_pc[t];
    float len = __ldg(&elen[e]);
    float v0 = __ldg(&evec[3 * e + 0]);
    float v1 = __ldg(&evec[3 * e + 1]);
    float v2 = __ldg(&evec[3 * e + 2]);
    float dot1 = fmaf(cf.x, ct.x, fmaf(cf.y, ct.y, cf.z * ct.z));
    float dot2 = fmaf(cf.x, v0, fmaf(cf.y, v1, cf.z * v2));
    g_rec[e] = make_float4(len, dot1, dot2, __int_as_float(f));
}

__global__ void k_wld(const float* __restrict__ Wm) {
    int j = threadIdx.x;
    if (j < 10) {
        g_w[j]      = Wm[100 + j];
        g_w[10 + j] = Wm[120 + j];
        g_w[20 + j] = Wm[130 + j];
    }
}

// ---- per-node h = state@Ws + b + sa*W11 (fp16-packed; no state copy) ----
__global__ void k_h(const float* __restrict__ Wm, const float* __restrict__ bm,
                    int N) {
    int n = blockIdx.x * blockDim.x + threadIdx.x;
    if (n >= N) return;
    const float4* srow = &g_state[n * 3];
    float4 s0 = srow[0], s1 = srow[1], s2 = srow[2];
    float s[10] = { s0.x, s0.y, s0.z, s0.w, s1.x, s1.y, s1.z, s1.w, s2.x, s2.y };
    float sa = g_pc[n].w;
    float h[10];
#pragma unroll
    for (int j = 0; j < 10; j++) {
        float acc = fmaf(sa, __ldg(&Wm[110 + j]), __ldg(&bm[j]));
#pragma unroll
        for (int i = 0; i < 10; i++)
            acc = fmaf(s[i], __ldg(&Wm[i * 10 + j]), acc);
        h[j] = acc;
    }
    store_h(n, h);
}

// ---- per-edge pass: 2 random gathers + 30 FMA + tanh + in-place REDs ----
__global__ void __launch_bounds__(256)
k_edge(const int* __restrict__ eto, int E, int T) {
    int tid = blockIdx.x * blockDim.x + threadIdx.x;
    float wl[10], w2[10], w3[10];
#pragma unroll
    for (int j = 0; j < 10; j++) {
        wl[j] = g_w[j];
        w2[j] = g_w[10 + j];
        w3[j] = g_w[20 + j];
    }
    float* stt = (float*)g_state;
    for (int e = tid; e < E; e += T) {
        float4 r = g_rec[e];
        int t = __ldg(&eto[e]);
        int f = __float_as_int(r.w);
        uint4 u = g_h8[f];
        unsigned int v = g_h9[f];
        float2 a0 = __half22float2(*(__half2*)&u.x);
        float2 a1 = __half22float2(*(__half2*)&u.y);
        float2 a2 = __half22float2(*(__half2*)&u.z);
        float2 a3 = __half22float2(*(__half2*)&u.w);
        float2 a4 = __half22float2(*(__half2*)&v);
        float hv[10] = { a0.x, a0.y, a1.x, a1.y, a2.x, a2.y, a3.x, a3.y, a4.x, a4.y };
        float m[10];
#pragma unroll
        for (int j = 0; j < 10; j++) {
            float a = fmaf(r.x, wl[j], fmaf(r.y, w2[j], fmaf(r.z, w3[j], hv[j])));
            m[j] = tanh_fast(a);
        }
        float* dst = stt + (size_t)t * SDP;
        red_add4(dst,     m[0], m[1], m[2], m[3]);
        red_add4(dst + 4, m[4], m[5], m[6], m[7]);
        red_add2(dst + 8, m[8], m[9]);
    }
}

// ---- graph segment sum ----
__global__ void k_graph(const int* __restrict__ gidx, int N) {
    int n = blockIdx.x * blockDim.x + threadIdx.x;
    if (n >= N) return;
    int g = gidx[n];
    const float4* srow = &g_state[n * 3];
    float4 s0 = srow[0], s1 = srow[1], s2 = srow[2];
    float* dst = (float*)&g_gs[g * 3];
    red_add4(dst,     s0.x, s0.y, s0.z, s0.w);
    red_add4(dst + 4, s1.x, s1.y, s1.z, s1.w);
    red_add2(dst + 8, s2.x, s2.y);
}

__device__ __forceinline__ float softplus_acc(float x) {
    if (x > 20.f) return x;
    return log1pf(expf(x));
}

__global__ void k_out(const float* __restrict__ Wo, const float* __restrict__ bo,
                      float* __restrict__ out, int G) {
    int g = blockIdx.x * blockDim.x + threadIdx.x;
    if (g >= G) return;
    const float* gs = (const float*)&g_gs[g * 3];
    float e[4];
#pragma unroll
    for (int j = 0; j < 4; j++) {
        float acc = __ldg(&bo[j]);
#pragma unroll
        for (int i = 0; i < 10; i++)
            acc = fmaf(gs[i], __ldg(&Wo[i * 4 + j]), acc);
        e[j] = acc;
    }
    out[4 * g + 0] = e[0];
    out[4 * g + 1] = softplus_acc(e[1]);
    out[4 * g + 2] = softplus_acc(e[2]) + 1.0f;
    out[4 * g + 3] = softplus_acc(e[3]);
}

extern "C" void kernel_launch(void* const* d_in, const int* in_sizes, int n_in,
                              void* d_out, int out_size) {
    const float* coords = (const float*)d_in[0];
    const float* elen   = (const float*)d_in[1];
    const float* evec   = (const float*)d_in[2];
    const float* Wm     = (const float*)d_in[3];
    const float* bm     = (const float*)d_in[4];
    const float* Wo     = (const float*)d_in[5];
    const float* bo     = (const float*)d_in[6];
    const int*   efrom  = (const int*)d_in[7];
    const int*   eto    = (const int*)d_in[8];
    const int*   gidx   = (const int*)d_in[9];
    float* out = (float*)d_out;

    int E = in_sizes[7];
    int N = in_sizes[9];
    int G = out_size / 4;

    const int TB = 256;
    int init_count = (N > GMAX) ? N : GMAX;
    int init_blocks = (init_count + TB - 1) / TB;
    int node_blocks = (N + TB - 1) / TB;
    int edge_blocks1 = (E + TB - 1) / TB;
    long ethreads = ((long)E + 3) / 4;              // 4 edges/thread
    int eblocks = (int)((ethreads + TB - 1) / TB);
    int T = eblocks * TB;
    int gblocks = (G + TB - 1) / TB;

    k_init<<<init_blocks, TB>>>(coords, Wm, bm, N);
    k_geo<<<edge_blocks1, TB>>>(efrom, eto, elen, evec, E);
    k_wld<<<1, 32>>>(Wm);

    // round 0 (h = h0 from init), REDs accumulate in place
    k_edge<<<eblocks, TB>>>(eto, E, T);
    // rounds 1, 2
    k_h<<<node_blocks, TB>>>(Wm, bm, N);
    k_edge<<<eblocks, TB>>>(eto, E, T);
    k_h<<<node_blocks, TB>>>(Wm, bm, N);
    k_edge<<<eblocks, TB>>>(eto, E, T);

    k_graph<<<node_blocks, TB>>>(gidx, N);
    k_out<<<gblocks, TB>>>(Wo, bo, out, G);
}

// round 7
// speedup vs baseline: 1.9216x; 1.1086x over previous
#include <cuda_runtime.h>
#include <cuda_fp16.h>
#include <math.h>

// ---------------------------------------------------------------------------
// EvidentialGNN3D — unsorted, geo-precomputed, in-place RED formulation.
//  Build once/launch (cheap, coalesced): rec[e] = (len, dot1, dot2, src).
//  Per round:
//    k_h   : h[n] = state[n]@Ws + b + sum|c_n|*W11  (fp16, ONE 32B sector/node)
//    k_edge: m = tanh(h[src] + geo@Wg); red.global.add.v4/v2 into state[dst]
//  Readout: graph segment sum + evidential head.
// ---------------------------------------------------------------------------

#define NMAX 200064
#define EMAX 6400000
#define GMAX 2048
#define SDP  12

struct __align__(32) HRow { uint4 a; uint2 b; uint2 pad; };

__device__ float4 g_state[NMAX * 3];   // (N,12) state, updated in place
__device__ HRow   g_hp[NMAX];          // h packed: 10 x fp16 in one 32B sector
__device__ float4 g_pc[NMAX];          // (x,y,z,sum|c|)
__device__ float4 g_gs[GMAX * 3];      // per-graph accum
__device__ float4 g_rec[EMAX];         // (len, dot1, dot2, src_as_int)
__device__ float  g_w[30];             // W rows 10 (len), 12 (dot1), 13 (dot2)

__device__ __forceinline__ float tanh_fast(float x) {
    float e = __expf(2.0f * x);
    return 1.0f - __fdividef(2.0f, e + 1.0f);
}
__device__ __forceinline__ void red_add4(float* p, float a, float b, float c, float d) {
    unsigned long long gp = __cvta_generic_to_global((void*)p);
    asm volatile("red.global.add.v4.f32 [%0], {%1,%2,%3,%4};"
                 :: "l"(gp), "f"(a), "f"(b), "f"(c), "f"(d) : "memory");
}
__device__ __forceinline__ void red_add2(float* p, float a, float b) {
    unsigned long long gp = __cvta_generic_to_global((void*)p);
    asm volatile("red.global.add.v2.f32 [%0], {%1,%2};"
                 :: "l"(gp), "f"(a), "f"(b) : "memory");
}

__device__ __forceinline__ void store_h(int n, const float* h) {
    __half2 p0 = __floats2half2_rn(h[0], h[1]);
    __half2 p1 = __floats2half2_rn(h[2], h[3]);
    __half2 p2 = __floats2half2_rn(h[4], h[5]);
    __half2 p3 = __floats2half2_rn(h[6], h[7]);
    __half2 p4 = __floats2half2_rn(h[8], h[9]);
    HRow r;
    r.a.x = *(unsigned int*)&p0;
    r.a.y = *(unsigned int*)&p1;
    r.a.z = *(unsigned int*)&p2;
    r.a.w = *(unsigned int*)&p3;
    r.b.x = *(unsigned int*)&p4;
    r.b.y = 0u;
    r.pad.x = 0u; r.pad.y = 0u;
    g_hp[n] = r;
}

// ---- init: pc, h0 = b + sum|c|*W11 (state=0), zero state & graph accum ----
__global__ void k_init(const float* __restrict__ coords,
                       const float* __restrict__ Wm, const float* __restrict__ bm,
                       int N) {
    int n = blockIdx.x * blockDim.x + threadIdx.x;
    float4 z4 = make_float4(0.f, 0.f, 0.f, 0.f);
    if (n < N) {
        float x = coords[3 * n + 0];
        float y = coords[3 * n + 1];
        float z = coords[3 * n + 2];
        float sa = fabsf(x) + fabsf(y) + fabsf(z);
        g_pc[n] = make_float4(x, y, z, sa);
        float h[10];
#pragma unroll
        for (int j = 0; j < 10; j++)
            h[j] = fmaf(sa, __ldg(&Wm[110 + j]), __ldg(&bm[j]));
        store_h(n, h);
        g_state[n * 3 + 0] = z4;
        g_state[n * 3 + 1] = z4;
        g_state[n * 3 + 2] = z4;
    }
    if (n < GMAX) {
        g_gs[n * 3 + 0] = z4;
        g_gs[n * 3 + 1] = z4;
        g_gs[n * 3 + 2] = z4;
    }
}

// ---- one-time geo precompute (coalesced write, original edge order) ----
__global__ void k_geo(const int* __restrict__ efrom, const int* __restrict__ eto,
                      const float* __restrict__ elen, const float* __restrict__ evec,
                      int E) {
    int e = blockIdx.x * blockDim.x + threadIdx.x;
    if (e >= E) return;
    int f = efrom[e];
    int t = eto[e];
    float4 cf = g_pc[f];
    float4 ct = g_pc[t];
    float len = __ldg(&elen[e]);
    float v0 = __ldg(&evec[3 * e + 0]);
    float v1 = __ldg(&evec[3 * e + 1]);
    float v2 = __ldg(&evec[3 * e + 2]);
    float dot1 = fmaf(cf.x, ct.x, fmaf(cf.y, ct.y, cf.z * ct.z));
    float dot2 = fmaf(cf.x, v0, fmaf(cf.y, v1, cf.z * v2));
    g_rec[e] = make_float4(len, dot1, dot2, __int_as_float(f));
}

__global__ void k_wld(const float* __restrict__ Wm) {
    int j = threadIdx.x;
    if (j < 10) {
        g_w[j]      = Wm[100 + j];
        g_w[10 + j] = Wm[120 + j];
        g_w[20 + j] = Wm[130 + j];
    }
}

// ---- per-node h = state@Ws + b + sa*W11 (fp16-packed) ----
__global__ void k_h(const float* __restrict__ Wm, const float* __restrict__ bm,
                    int N) {
    int n = blockIdx.x * blockDim.x + threadIdx.x;
    if (n >= N) return;
    const float4* srow = &g_state[n * 3];
    float4 s0 = srow[0], s1 = srow[1], s2 = srow[2];
    float s[10] = { s0.x, s0.y, s0.z, s0.w, s1.x, s1.y, s1.z, s1.w, s2.x, s2.y };
    float sa = g_pc[n].w;
    float h[10];
#pragma unroll
    for (int j = 0; j < 10; j++) {
        float acc = fmaf(sa, __ldg(&Wm[110 + j]), __ldg(&bm[j]));
#pragma unroll
        for (int i = 0; i < 10; i++)
            acc = fmaf(s[i], __ldg(&Wm[i * 10 + j]), acc);
        h[j] = acc;
    }
    store_h(n, h);
}

// ---- per-edge pass: 1-sector h gather + 30 FMA + tanh + in-place REDs ----
__global__ void __launch_bounds__(256)
k_edge(const int* __restrict__ eto, int E, int T) {
    int tid = blockIdx.x * blockDim.x + threadIdx.x;
    float wl[10], w2[10], w3[10];
#pragma unroll
    for (int j = 0; j < 10; j++) {
        wl[j] = g_w[j];
        w2[j] = g_w[10 + j];
        w3[j] = g_w[20 + j];
    }
    float* stt = (float*)g_state;
    for (int e = tid; e < E; e += T) {
        float4 r = __ldcs(&g_rec[e]);            // streaming: evict-first
        int t = __ldcs(&eto[e]);
        int f = __float_as_int(r.w);
        const HRow* hp = &g_hp[f];
        uint4 u = __ldg(&hp->a);                 // same 32B sector
        uint2 v = __ldg(&hp->b);
        float2 a0 = __half22float2(*(__half2*)&u.x);
        float2 a1 = __half22float2(*(__half2*)&u.y);
        float2 a2 = __half22float2(*(__half2*)&u.z);
        float2 a3 = __half22float2(*(__half2*)&u.w);
        float2 a4 = __half22float2(*(__half2*)&v.x);
        float hv[10] = { a0.x, a0.y, a1.x, a1.y, a2.x, a2.y, a3.x, a3.y, a4.x, a4.y };
        float m[10];
#pragma unroll
        for (int j = 0; j < 10; j++) {
            float a = fmaf(r.x, wl[j], fmaf(r.y, w2[j], fmaf(r.z, w3[j], hv[j])));
            m[j] = tanh_fast(a);
        }
        float* dst = stt + (size_t)t * SDP;
        red_add4(dst,     m[0], m[1], m[2], m[3]);
        red_add4(dst + 4, m[4], m[5], m[6], m[7]);
        red_add2(dst + 8, m[8], m[9]);
    }
}

// ---- graph segment sum ----
__global__ void k_graph(const int* __restrict__ gidx, int N) {
    int n = blockIdx.x * blockDim.x + threadIdx.x;
    if (n >= N) return;
    int g = gidx[n];
    const float4* srow = &g_state[n * 3];
    float4 s0 = srow[0], s1 = srow[1], s2 = srow[2];
    float* dst = (float*)&g_gs[g * 3];
    red_add4(dst,     s0.x, s0.y, s0.z, s0.w);
    red_add4(dst + 4, s1.x, s1.y, s1.z, s1.w);
    red_add2(dst + 8, s2.x, s2.y);
}

__device__ __forceinline__ float softplus_acc(float x) {
    if (x > 20.f) return x;
    return log1pf(expf(x));
}

__global__ void k_out(const float* __restrict__ Wo, const float* __restrict__ bo,
                      float* __restrict__ out, int G) {
    int g = blockIdx.x * blockDim.x + threadIdx.x;
    if (g >= G) return;
    const float* gs = (const float*)&g_gs[g * 3];
    float e[4];
#pragma unroll
    for (int j = 0; j < 4; j++) {
        float acc = __ldg(&bo[j]);
#pragma unroll
        for (int i = 0; i < 10; i++)
            acc = fmaf(gs[i], __ldg(&Wo[i * 4 + j]), acc);
        e[j] = acc;
    }
    out[4 * g + 0] = e[0];
    out[4 * g + 1] = softplus_acc(e[1]);
    out[4 * g + 2] = softplus_acc(e[2]) + 1.0f;
    out[4 * g + 3] = softplus_acc(e[3]);
}

extern "C" void kernel_launch(void* const* d_in, const int* in_sizes, int n_in,
                              void* d_out, int out_size) {
    const float* coords = (const float*)d_in[0];
    const float* elen   = (const float*)d_in[1];
    const float* evec   = (const float*)d_in[2];
    const float* Wm     = (const float*)d_in[3];
    const float* bm     = (const float*)d_in[4];
    const float* Wo     = (const float*)d_in[5];
    const float* bo     = (const float*)d_in[6];
    const int*   efrom  = (const int*)d_in[7];
    const int*   eto    = (const int*)d_in[8];
    const int*   gidx   = (const int*)d_in[9];
    float* out = (float*)d_out;

    int E = in_sizes[7];
    int N = in_sizes[9];
    int G = out_size / 4;

    const int TB = 256;
    int init_count = (N > GMAX) ? N : GMAX;
    int init_blocks = (init_count + TB - 1) / TB;
    int node_blocks = (N + TB - 1) / TB;
    int edge_blocks1 = (E + TB - 1) / TB;
    long ethreads = ((long)E + 3) / 4;              // 4 edges/thread
    int eblocks = (int)((ethreads + TB - 1) / TB);
    int T = eblocks * TB;
    int gblocks = (G + TB - 1) / TB;

    k_init<<<init_blocks, TB>>>(coords, Wm, bm, N);
    k_geo<<<edge_blocks1, TB>>>(efrom, eto, elen, evec, E);
    k_wld<<<1, 32>>>(Wm);

    // round 0 (h = h0 from init), REDs accumulate in place
    k_edge<<<eblocks, TB>>>(eto, E, T);
    // rounds 1, 2
    k_h<<<node_blocks, TB>>>(Wm, bm, N);
    k_edge<<<eblocks, TB>>>(eto, E, T);
    k_h<<<node_blocks, TB>>>(Wm, bm, N);
    k_edge<<<eblocks, TB>>>(eto, E, T);

    k_graph<<<node_blocks, TB>>>(gidx, N);
    k_out<<<gblocks, TB>>>(Wo, bo, out, G);
}